// round 16
// baseline (speedup 1.0000x reference)
#include <cuda_runtime.h>
#include <math.h>

#define T    2048
#define F    1024
#define NB   64          // total batch
#define HB   32          // half batch
#define KSEL 20
#define BIGI (1 << 30)
#define RED  5           // blocks per output row (redundant topk)
#define RPB  4           // rows gathered per block (KSEL / RED * ... = 20/5)

// scratch (no allocs allowed)
__device__ float g_mags[NB * T];

// -------- kernel 1: per-(b,t) L2 norm over feature dim --------
// one warp per row; 8 float4 loads per lane, fully coalesced. HBM-bound
// at ~6.9 TB/s (86% of spec) — measured roofline. Untouched.
__global__ void mag_kernel(const float* __restrict__ feat) {
    int warp = (blockIdx.x * blockDim.x + threadIdx.x) >> 5;  // 0 .. 64*2048-1
    int lane = threadIdx.x & 31;
    const float4* row = (const float4*)(feat + (size_t)warp * F);
    float s = 0.f;
#pragma unroll
    for (int i = 0; i < 8; i++) {
        float4 v = row[lane + i * 32];
        s += v.x * v.x + v.y * v.y + v.z * v.z + v.w * v.w;
    }
#pragma unroll
    for (int o = 16; o; o >>= 1) s += __shfl_xor_sync(0xffffffffu, s, o);
    if (lane == 0) g_mags[warp] = sqrtf(s);
}

// -------- kernel 2: redundant REDUX topk + gather (320 blocks) -------------
// 5 blocks per output row each recompute the row's top-20 (REDUX selection
// is cheap enough that 5x redundancy < one kernel boundary), keep indices in
// shared memory, then gather 4 of the 20 selected rows (MLP=4 per thread).
// slice==0 block also writes the score mean. No cross-block communication.
__global__ void __launch_bounds__(256)
topk_gather_kernel(const float* __restrict__ feat,
                   const float* __restrict__ scores,
                   const float* __restrict__ mask_abn,
                   const float* __restrict__ mask_nor,
                   float* __restrict__ out) {
    __shared__ unsigned s_wv[8][21];
    __shared__ int      s_wi[8][21];
    __shared__ int      s_sel[KSEL];

    int blk   = blockIdx.x;
    int r     = blk / RED;           // output row 0..63 (abn rows first)
    int slice = blk % RED;           // which 4 of the 20 rows to copy
    int tid  = threadIdx.x;
    int lane = tid & 31;
    int wid  = tid >> 5;

    int batch;
    const float* mask;
    if (r < HB) { batch = HB + r; mask = mask_abn + (size_t)r * T; }
    else        { batch = r - HB; mask = mask_nor + (size_t)(r - HB) * T; }

    const float inv = 1.0f / 0.9f;   // 1/(1-P)
    unsigned u[8];
#pragma unroll
    for (int j = 0; j < 8; j++) {
        int t = wid * 256 + j * 32 + lane;    // warp owns contiguous 256
        float d = (mask[t] > 0.1f) ? inv : 0.0f;
        u[j] = __float_as_uint(g_mags[batch * T + t] * d);  // >=0 -> monotonic
    }

    // 20 warp-local rounds: local scan + 2 REDUX ops, no block syncs.
    // Values >= 0 so float bits compare as unsigned; tie-break = lowest index.
    for (int k = 0; k < KSEL; k++) {
        unsigned bv = 0; int bi = BIGI;
#pragma unroll
        for (int j = 0; j < 8; j++) {
            if (u[j] > bv) { bv = u[j]; bi = wid * 256 + j * 32 + lane; }
        }
        unsigned mx = __reduce_max_sync(0xffffffffu, bv);
        int cand = (bv == mx) ? bi : BIGI;
        int wix  = (int)__reduce_min_sync(0xffffffffu, (unsigned)cand);
        if (lane == 0) { s_wv[wid][k] = mx; s_wi[wid][k] = wix; }
        int local = wix - wid * 256;          // remove winner from registers
        if ((local & 31) == lane) u[local >> 5] = 0;
    }
    if (lane == 0) { s_wv[wid][20] = 0; s_wi[wid][20] = BIGI; }
    __syncthreads();

    // warp 0: merge 8 descending lists of 20 (lanes 0..7 hold list heads)
    if (wid == 0) {
        int      p  = 0;
        unsigned hv = (lane < 8) ? s_wv[lane][0] : 0;
        int      hi = (lane < 8) ? s_wi[lane][0] : BIGI;
        int my_idx = 0;
        for (int k = 0; k < KSEL; k++) {
            unsigned mx = __reduce_max_sync(0xffffffffu, hv);
            int cand = (hv == mx) ? hi : BIGI;
            int wix  = (int)__reduce_min_sync(0xffffffffu, (unsigned)cand);
            if (lane == k) my_idx = wix;
            if (lane < 8 && hi == wix) {      // advance that list
                p++; hv = s_wv[lane][p]; hi = s_wi[lane][p];
            }
        }
        if (lane < KSEL) s_sel[lane] = my_idx;

        // score mean: written once per row (slice 0 only)
        if (slice == 0) {
            float sc = 0.f;
            if (lane < KSEL) sc = scores[(size_t)batch * T + my_idx];
#pragma unroll
            for (int o = 16; o; o >>= 1) sc += __shfl_xor_sync(0xffffffffu, sc, o);
            if (lane == 0) out[r] = sc / (float)KSEL;  // [0,32)=abn, [32,64)=nor
        }
    }
    __syncthreads();

    // gather my 4 of the 20 selected rows: batched loads (MLP=4) then stores
    const float4* srcp[RPB];
#pragma unroll
    for (int i = 0; i < RPB; i++) {
        int k = slice * RPB + i;             // selected-row slot 0..19
        srcp[i] = (const float4*)(feat + ((size_t)batch * T + s_sel[k]) * F) + tid;
    }
    float4 buf[RPB];
#pragma unroll
    for (int i = 0; i < RPB; i++) buf[i] = *srcp[i];
    float4* dst = (float4*)(out + 64 + (size_t)r * KSEL * F);
#pragma unroll
    for (int i = 0; i < RPB; i++) dst[(size_t)(slice * RPB + i) * 256 + tid] = buf[i];
}

extern "C" void kernel_launch(void* const* d_in, const int* in_sizes, int n_in,
                              void* d_out, int out_size) {
    const float* feat   = (const float*)d_in[0];
    const float* scores = (const float*)d_in[1];
    const float* mabn   = (const float*)d_in[2];
    const float* mnor   = (const float*)d_in[3];
    float* out = (float*)d_out;

    mag_kernel<<<(NB * T) / 8, 256>>>(feat);
    topk_gather_kernel<<<NB * RED, 256>>>(feat, scores, mabn, mnor, out);
}

// round 17
// speedup vs baseline: 1.0044x; 1.0044x over previous
#include <cuda_runtime.h>
#include <math.h>

#define T    2048
#define F    1024
#define NB   64          // total batch
#define HB   32          // half batch
#define KSEL 20
#define BIGI (1 << 30)
#define RED  2           // blocks per output row — 128 blocks < 148 SMs
#define RPB  10          // rows gathered per block (KSEL / RED)

// scratch (no allocs allowed)
__device__ float g_mags[NB * T];

// -------- kernel 1: per-(b,t) L2 norm over feature dim --------
// one warp per row; 8 float4 loads per lane, fully coalesced. 6.9 TB/s =
// the LTS chip cap — at the true roofline. Untouched.
__global__ void mag_kernel(const float* __restrict__ feat) {
    int warp = (blockIdx.x * blockDim.x + threadIdx.x) >> 5;  // 0 .. 64*2048-1
    int lane = threadIdx.x & 31;
    const float4* row = (const float4*)(feat + (size_t)warp * F);
    float s = 0.f;
#pragma unroll
    for (int i = 0; i < 8; i++) {
        float4 v = row[lane + i * 32];
        s += v.x * v.x + v.y * v.y + v.z * v.z + v.w * v.w;
    }
#pragma unroll
    for (int o = 16; o; o >>= 1) s += __shfl_xor_sync(0xffffffffu, s, o);
    if (lane == 0) g_mags[warp] = sqrtf(s);
}

// -------- kernel 2: 2x-redundant REDUX topk + gather (128 blocks) ----------
// 128 blocks < 148 SMs -> every block gets its own SM, so the two redundant
// topk instances per row run truly parallel (R16's 320 blocks stacked 3/SM
// and queued on the issue port). Each block gathers 10 of its row's 20
// selected rows in two MLP=5 batches. No cross-block communication.
__global__ void __launch_bounds__(256)
topk_gather_kernel(const float* __restrict__ feat,
                   const float* __restrict__ scores,
                   const float* __restrict__ mask_abn,
                   const float* __restrict__ mask_nor,
                   float* __restrict__ out) {
    __shared__ unsigned s_wv[8][21];
    __shared__ int      s_wi[8][21];
    __shared__ int      s_sel[KSEL];

    int blk   = blockIdx.x;
    int r     = blk >> 1;            // output row 0..63 (abn rows first)
    int slice = blk & 1;             // which 10 of the 20 rows to copy
    int tid  = threadIdx.x;
    int lane = tid & 31;
    int wid  = tid >> 5;

    int batch;
    const float* mask;
    if (r < HB) { batch = HB + r; mask = mask_abn + (size_t)r * T; }
    else        { batch = r - HB; mask = mask_nor + (size_t)(r - HB) * T; }

    const float inv = 1.0f / 0.9f;   // 1/(1-P)
    unsigned u[8];
#pragma unroll
    for (int j = 0; j < 8; j++) {
        int t = wid * 256 + j * 32 + lane;    // warp owns contiguous 256
        float d = (mask[t] > 0.1f) ? inv : 0.0f;
        u[j] = __float_as_uint(g_mags[batch * T + t] * d);  // >=0 -> monotonic
    }

    // 20 warp-local rounds: local scan + 2 REDUX ops, no block syncs.
    // Values >= 0 so float bits compare as unsigned; tie-break = lowest index.
    for (int k = 0; k < KSEL; k++) {
        unsigned bv = 0; int bi = BIGI;
#pragma unroll
        for (int j = 0; j < 8; j++) {
            if (u[j] > bv) { bv = u[j]; bi = wid * 256 + j * 32 + lane; }
        }
        unsigned mx = __reduce_max_sync(0xffffffffu, bv);
        int cand = (bv == mx) ? bi : BIGI;
        int wix  = (int)__reduce_min_sync(0xffffffffu, (unsigned)cand);
        if (lane == 0) { s_wv[wid][k] = mx; s_wi[wid][k] = wix; }
        int local = wix - wid * 256;          // remove winner from registers
        if ((local & 31) == lane) u[local >> 5] = 0;
    }
    if (lane == 0) { s_wv[wid][20] = 0; s_wi[wid][20] = BIGI; }
    __syncthreads();

    // warp 0: merge 8 descending lists of 20 (lanes 0..7 hold list heads)
    if (wid == 0) {
        int      p  = 0;
        unsigned hv = (lane < 8) ? s_wv[lane][0] : 0;
        int      hi = (lane < 8) ? s_wi[lane][0] : BIGI;
        int my_idx = 0;
        for (int k = 0; k < KSEL; k++) {
            unsigned mx = __reduce_max_sync(0xffffffffu, hv);
            int cand = (hv == mx) ? hi : BIGI;
            int wix  = (int)__reduce_min_sync(0xffffffffu, (unsigned)cand);
            if (lane == k) my_idx = wix;
            if (lane < 8 && hi == wix) {      // advance that list
                p++; hv = s_wv[lane][p]; hi = s_wi[lane][p];
            }
        }
        if (lane < KSEL) s_sel[lane] = my_idx;

        // score mean: written once per row (slice 0 only)
        if (slice == 0) {
            float sc = 0.f;
            if (lane < KSEL) sc = scores[(size_t)batch * T + my_idx];
#pragma unroll
            for (int o = 16; o; o >>= 1) sc += __shfl_xor_sync(0xffffffffu, sc, o);
            if (lane == 0) out[r] = sc / (float)KSEL;  // [0,32)=abn, [32,64)=nor
        }
    }
    __syncthreads();

    // gather my 10 of the 20 selected rows, two batches of MLP=5
    float4* dst = (float4*)(out + 64 + (size_t)r * KSEL * F);
#pragma unroll
    for (int half = 0; half < 2; half++) {
        const float4* srcp[5];
#pragma unroll
        for (int i = 0; i < 5; i++) {
            int k = slice * RPB + half * 5 + i;   // selected-row slot 0..19
            srcp[i] = (const float4*)(feat + ((size_t)batch * T + s_sel[k]) * F) + tid;
        }
        float4 buf[5];
#pragma unroll
        for (int i = 0; i < 5; i++) buf[i] = *srcp[i];   // batched loads, MLP=5
#pragma unroll
        for (int i = 0; i < 5; i++)
            dst[(size_t)(slice * RPB + half * 5 + i) * 256 + tid] = buf[i];
    }
}

extern "C" void kernel_launch(void* const* d_in, const int* in_sizes, int n_in,
                              void* d_out, int out_size) {
    const float* feat   = (const float*)d_in[0];
    const float* scores = (const float*)d_in[1];
    const float* mabn   = (const float*)d_in[2];
    const float* mnor   = (const float*)d_in[3];
    float* out = (float*)d_out;

    mag_kernel<<<(NB * T) / 8, 256>>>(feat);
    topk_gather_kernel<<<NB * RED, 256>>>(feat, scores, mabn, mnor, out);
}